// round 6
// baseline (speedup 1.0000x reference)
#include <cuda_runtime.h>
#include <cuda_bf16.h>
#include <stdint.h>
#include <math.h>

#define N_TOK 2048
#define HDIM  256
#define NHEAD 8
#define DHEAD 32
#define FFDIM 512
#define NLAYER 6
#define CAP   96

// -------- device scratch (no allocations allowed) --------
__device__ float g_X  [N_TOK * HDIM];
__device__ float g_Hn [N_TOK * HDIM];
__device__ float g_QKV[N_TOK * 3 * HDIM];
__device__ float g_ATT[N_TOK * HDIM];
__device__ float g_FF [N_TOK * FFDIM];
__device__ float g_T1 [N_TOK * HDIM];
__device__ float g_T2 [N_TOK * (HDIM/2)];
__device__ float g_eta[N_TOK];
__device__ float g_phi[N_TOK];
__device__ int   g_nbr[N_TOK * CAP];
__device__ int   g_cnt[N_TOK];

// -------- embed: x = x_raw @ Win^T + b_in ; also eta/phi --------
__global__ void embed_kernel(const float* __restrict__ xr,
                             const float* __restrict__ Win,
                             const float* __restrict__ b_in) {
    int n = blockIdx.x;
    int h = threadIdx.x;               // 256
    __shared__ float r[8];
    if (h < 8) r[h] = xr[n * 8 + h];
    __syncthreads();
    float acc = b_in[h];
#pragma unroll
    for (int k = 0; k < 8; k++) acc += r[k] * Win[h * 8 + k];
    g_X[n * HDIM + h] = acc;
    if (h == 0) {
        g_eta[n] = r[1] * 5.24f   - 2.62f;
        g_phi[n] = r[2] * 6.2832f - 3.1416f;
    }
}

// -------- neighbor list build (deterministic, ordered) --------
__global__ void build_nbr_kernel() {
    int warp = (blockIdx.x * blockDim.x + threadIdx.x) >> 5;
    int lane = threadIdx.x & 31;
    if (warp >= N_TOK) return;
    int i = warp;
    float ei = g_eta[i], pi = g_phi[i];
    int c = 0;
    for (int j0 = 0; j0 < N_TOK; j0 += 32) {
        int j = j0 + lane;
        float de = ei - g_eta[j];
        float dp = pi - g_phi[j];
        dp = dp - 6.283185307179586f * rintf(dp * 0.15915494309189535f);
        float dr2 = de * de + dp * dp;
        bool keep = (dr2 <= 0.04f);
        unsigned m = __ballot_sync(0xffffffffu, keep);
        if (keep) {
            int pos = c + __popc(m & ((1u << lane) - 1u));
            if (pos < CAP) g_nbr[i * CAP + pos] = j;
        }
        c += __popc(m);
    }
    if (lane == 0) g_cnt[i] = (c < CAP) ? c : CAP;
}

// -------- LayerNorm over H=256 (one block per row) --------
__global__ void ln_kernel(const float* __restrict__ x,
                          const float* __restrict__ g,
                          const float* __restrict__ b,
                          float* __restrict__ out) {
    int n = blockIdx.x;
    int t = threadIdx.x;               // 256
    __shared__ float r1[8], r2[8];
    float v = x[n * HDIM + t];
    float s = v;
#pragma unroll
    for (int off = 16; off; off >>= 1) s += __shfl_xor_sync(0xffffffffu, s, off);
    if ((t & 31) == 0) r1[t >> 5] = s;
    __syncthreads();
    float tot = 0.f;
#pragma unroll
    for (int w = 0; w < 8; w++) tot += r1[w];
    float mean = tot * (1.f / 256.f);
    float d = v - mean;
    float s2 = d * d;
#pragma unroll
    for (int off = 16; off; off >>= 1) s2 += __shfl_xor_sync(0xffffffffu, s2, off);
    if ((t & 31) == 0) r2[t >> 5] = s2;
    __syncthreads();
    float vtot = 0.f;
#pragma unroll
    for (int w = 0; w < 8; w++) vtot += r2[w];
    float var = vtot * (1.f / 256.f);
    out[n * HDIM + t] = d * rsqrtf(var + 1e-5f) * g[t] + b[t];
}

// -------- 3xTF32 tensor-core GEMM: C[M,N] = A[M,K] @ B[N,K]^T + bias (+relu)(+resid)
// Requires M%64==0, N%64==0, K%16==0. 128 threads, 4 warps (2x2), warp tile 32x32.
__device__ __forceinline__ void mma_tf32(float c[4],
                                         unsigned a0, unsigned a1, unsigned a2, unsigned a3,
                                         unsigned b0, unsigned b1) {
    asm volatile(
        "mma.sync.aligned.m16n8k8.row.col.f32.tf32.tf32.f32 "
        "{%0,%1,%2,%3}, {%4,%5,%6,%7}, {%8,%9}, {%0,%1,%2,%3};\n"
        : "+f"(c[0]), "+f"(c[1]), "+f"(c[2]), "+f"(c[3])
        : "r"(a0), "r"(a1), "r"(a2), "r"(a3), "r"(b0), "r"(b1));
}

__device__ __forceinline__ void split_tf32(float x, unsigned& hi, unsigned& lo) {
    unsigned h = __float_as_uint(x) & 0xffffe000u;   // exact tf32-representable head
    hi = h;
    lo = __float_as_uint(x - __uint_as_float(h));    // exact residual (<=13 mantissa bits)
}

template<bool RELU, bool RES>
__global__ void __launch_bounds__(128)
tgemm_kernel(const float* __restrict__ A, const float* __restrict__ B,
             const float* __restrict__ bias, const float* __restrict__ R,
             float* __restrict__ C, int M, int Ncols, int K) {
    __shared__ float As[64][20];   // [m][k], pad 4 -> conflict-free frag reads
    __shared__ float Bs[64][20];   // [n][k]

    int tid  = threadIdx.x;
    int lane = tid & 31;
    int warp = tid >> 5;
    int wm = (warp >> 1) * 32;     // warp row offset in tile
    int wn = (warp & 1)  * 32;     // warp col offset in tile
    int g = lane >> 2;             // 0..7
    int t = lane & 3;              // 0..3

    int m0 = blockIdx.y * 64;
    int n0 = blockIdx.x * 64;

    float acc[2][4][4];
#pragma unroll
    for (int mt = 0; mt < 2; mt++)
#pragma unroll
        for (int nt = 0; nt < 4; nt++)
#pragma unroll
            for (int r = 0; r < 4; r++) acc[mt][nt][r] = 0.f;

    int lr = tid >> 2;             // 0..31
    int lc = (tid & 3) * 4;        // 0,4,8,12
    const float* Ag  = A + (size_t)(m0 + lr) * K + lc;
    const float* Ag2 = Ag + (size_t)32 * K;
    const float* Bg  = B + (size_t)(n0 + lr) * K + lc;
    const float* Bg2 = Bg + (size_t)32 * K;

    for (int k0 = 0; k0 < K; k0 += 16) {
        float4 av0 = *(const float4*)(Ag  + k0);
        float4 av1 = *(const float4*)(Ag2 + k0);
        float4 bv0 = *(const float4*)(Bg  + k0);
        float4 bv1 = *(const float4*)(Bg2 + k0);
        *(float4*)&As[lr     ][lc] = av0;
        *(float4*)&As[lr + 32][lc] = av1;
        *(float4*)&Bs[lr     ][lc] = bv0;
        *(float4*)&Bs[lr + 32][lc] = bv1;
        __syncthreads();

#pragma unroll
        for (int kk = 0; kk < 2; kk++) {
            int kb = kk * 8;
            // A fragments: a0:(g,t) a1:(g+8,t) a2:(g,t+4) a3:(g+8,t+4)
            float af[2][4];
#pragma unroll
            for (int mt = 0; mt < 2; mt++) {
                int rb = wm + mt * 16 + g;
                af[mt][0] = As[rb    ][kb + t];
                af[mt][1] = As[rb + 8][kb + t];
                af[mt][2] = As[rb    ][kb + t + 4];
                af[mt][3] = As[rb + 8][kb + t + 4];
            }
            // B fragments: b0:(k=t,n=g) b1:(k=t+4,n=g)
            float bf[4][2];
#pragma unroll
            for (int nt = 0; nt < 4; nt++) {
                int nb = wn + nt * 8 + g;
                bf[nt][0] = Bs[nb][kb + t];
                bf[nt][1] = Bs[nb][kb + t + 4];
            }
            unsigned ah[2][4], al[2][4], bh[4][2], bl[4][2];
#pragma unroll
            for (int mt = 0; mt < 2; mt++)
#pragma unroll
                for (int r = 0; r < 4; r++) split_tf32(af[mt][r], ah[mt][r], al[mt][r]);
#pragma unroll
            for (int nt = 0; nt < 4; nt++)
#pragma unroll
                for (int r = 0; r < 2; r++) split_tf32(bf[nt][r], bh[nt][r], bl[nt][r]);

#pragma unroll
            for (int mt = 0; mt < 2; mt++)
#pragma unroll
                for (int nt = 0; nt < 4; nt++) {
                    mma_tf32(acc[mt][nt], ah[mt][0], ah[mt][1], ah[mt][2], ah[mt][3],
                             bh[nt][0], bh[nt][1]);
                    mma_tf32(acc[mt][nt], ah[mt][0], ah[mt][1], ah[mt][2], ah[mt][3],
                             bl[nt][0], bl[nt][1]);
                    mma_tf32(acc[mt][nt], al[mt][0], al[mt][1], al[mt][2], al[mt][3],
                             bh[nt][0], bh[nt][1]);
                }
        }
        __syncthreads();
    }

    // epilogue: c0:(g,2t) c1:(g,2t+1) c2:(g+8,2t) c3:(g+8,2t+1)
#pragma unroll
    for (int mt = 0; mt < 2; mt++) {
#pragma unroll
        for (int half = 0; half < 2; half++) {
            int row = m0 + wm + mt * 16 + g + half * 8;
#pragma unroll
            for (int nt = 0; nt < 4; nt++) {
                int col = n0 + wn + nt * 8 + 2 * t;
                float v0 = acc[mt][nt][half * 2 + 0] + bias[col];
                float v1 = acc[mt][nt][half * 2 + 1] + bias[col + 1];
                if (RELU) { v0 = fmaxf(v0, 0.f); v1 = fmaxf(v1, 0.f); }
                if (RES) {
                    v0 += R[(size_t)row * Ncols + col];
                    v1 += R[(size_t)row * Ncols + col + 1];
                }
                float2 o = make_float2(v0, v1);
                *(float2*)&C[(size_t)row * Ncols + col] = o;
            }
        }
    }
}

// -------- scalar tiled SGEMM (kept for small-N head) --------
template<bool RELU, bool RES>
__global__ void gemm_kernel(const float* __restrict__ A, const float* __restrict__ B,
                            const float* __restrict__ bias, const float* __restrict__ R,
                            float* __restrict__ C, int M, int Ncols, int K) {
    __shared__ __align__(16) float As[16][68];
    __shared__ __align__(16) float Bs[16][68];
    int tx = threadIdx.x, ty = threadIdx.y;            // 16 x 16
    int tid = ty * 16 + tx;
    int m0 = blockIdx.y * 64, n0 = blockIdx.x * 64;
    int lr = tid >> 2;
    int lc = (tid & 3) * 4;

    float acc[4][4];
#pragma unroll
    for (int i = 0; i < 4; i++)
#pragma unroll
        for (int j = 0; j < 4; j++) acc[i][j] = 0.f;

    const float* Ag = A + (size_t)(m0 + lr) * K + lc;
    bool bvalid = (n0 + lr) < Ncols;
    const float* Bg = B + (size_t)(n0 + lr) * K + lc;

    for (int k0 = 0; k0 < K; k0 += 16) {
        float4 av = *(const float4*)(Ag + k0);
        float4 bv = bvalid ? *(const float4*)(Bg + k0) : make_float4(0.f, 0.f, 0.f, 0.f);
        As[lc + 0][lr] = av.x; As[lc + 1][lr] = av.y;
        As[lc + 2][lr] = av.z; As[lc + 3][lr] = av.w;
        Bs[lc + 0][lr] = bv.x; Bs[lc + 1][lr] = bv.y;
        Bs[lc + 2][lr] = bv.z; Bs[lc + 3][lr] = bv.w;
        __syncthreads();
#pragma unroll
        for (int kk = 0; kk < 16; kk++) {
            float4 a = *(const float4*)&As[kk][ty * 4];
            float4 b = *(const float4*)&Bs[kk][tx * 4];
            acc[0][0] += a.x * b.x; acc[0][1] += a.x * b.y; acc[0][2] += a.x * b.z; acc[0][3] += a.x * b.w;
            acc[1][0] += a.y * b.x; acc[1][1] += a.y * b.y; acc[1][2] += a.y * b.z; acc[1][3] += a.y * b.w;
            acc[2][0] += a.z * b.x; acc[2][1] += a.z * b.y; acc[2][2] += a.z * b.z; acc[2][3] += a.z * b.w;
            acc[3][0] += a.w * b.x; acc[3][1] += a.w * b.y; acc[3][2] += a.w * b.z; acc[3][3] += a.w * b.w;
        }
        __syncthreads();
    }

#pragma unroll
    for (int i = 0; i < 4; i++) {
        int row = m0 + ty * 4 + i;
#pragma unroll
        for (int j = 0; j < 4; j++) {
            int col = n0 + tx * 4 + j;
            if (col < Ncols) {
                float v = acc[i][j] + bias[col];
                if (RELU) v = fmaxf(v, 0.f);
                if (RES)  v += R[(size_t)row * Ncols + col];
                C[(size_t)row * Ncols + col] = v;
            }
        }
    }
}

// -------- sparse attention: one warp per (query, head) --------
__global__ void attn_kernel() {
    int warp = (blockIdx.x * blockDim.x + threadIdx.x) >> 5;
    int lane = threadIdx.x & 31;
    int n = warp >> 3;
    int h = warp & 7;
    if (n >= N_TOK) return;
    const float scale = 0.17677669529663687f;   // 1/sqrt(32)
    float q = g_QKV[n * 768 + h * 32 + lane];
    int c = g_cnt[n];
    float m = -1e30f, s = 0.f, o = 0.f;
    for (int t = 0; t < c; t++) {
        int j = g_nbr[n * CAP + t];
        float kv = g_QKV[j * 768 + 256 + h * 32 + lane];
        float prod = q * kv;
#pragma unroll
        for (int off = 16; off; off >>= 1) prod += __shfl_xor_sync(0xffffffffu, prod, off);
        float sc = prod * scale;
        float mn = fmaxf(m, sc);
        float corr = __expf(m - mn);
        float p = __expf(sc - mn);
        s = s * corr + p;
        float v = g_QKV[j * 768 + 512 + h * 32 + lane];
        o = o * corr + p * v;
        m = mn;
    }
    g_ATT[n * 256 + h * 32 + lane] = o / s;
}

// -------- beta head: zb = T2 @ Wb2^T + bb2 ; beta = clip(sigmoid(zb)) --------
__global__ void beta_kernel(const float* __restrict__ Wb2,
                            const float* __restrict__ bb2,
                            float* __restrict__ out) {
    int warp = (blockIdx.x * blockDim.x + threadIdx.x) >> 5;
    int lane = threadIdx.x & 31;
    if (warp >= N_TOK) return;
    float s = 0.f;
#pragma unroll
    for (int k = lane; k < 128; k += 32) s += g_T2[warp * 128 + k] * Wb2[k];
#pragma unroll
    for (int off = 16; off; off >>= 1) s += __shfl_xor_sync(0xffffffffu, s, off);
    if (lane == 0) {
        float z = s + bb2[0];
        float b = 1.f / (1.f + expf(-z));
        b = fminf(fmaxf(b, 1e-6f), 1.f - 1e-6f);
        out[warp] = b;
    }
}

extern "C" void kernel_launch(void* const* d_in, const int* in_sizes, int n_in,
                              void* d_out, int out_size) {
    const float* x_raw = (const float*)d_in[0];
    // d_in[1] = batch (unused)
    const float* Win  = (const float*)d_in[2];
    const float* b_in = (const float*)d_in[3];
    const float* Wqkv = (const float*)d_in[4];
    const float* bqkv = (const float*)d_in[5];
    const float* Wo   = (const float*)d_in[6];
    const float* bo   = (const float*)d_in[7];
    const float* W1   = (const float*)d_in[8];
    const float* b1   = (const float*)d_in[9];
    const float* W2   = (const float*)d_in[10];
    const float* b2   = (const float*)d_in[11];
    const float* g1   = (const float*)d_in[12];
    const float* be1  = (const float*)d_in[13];
    const float* g2   = (const float*)d_in[14];
    const float* be2  = (const float*)d_in[15];
    const float* Wl1  = (const float*)d_in[16];
    const float* bl1  = (const float*)d_in[17];
    const float* Wl2  = (const float*)d_in[18];
    const float* bl2  = (const float*)d_in[19];
    const float* Wb1  = (const float*)d_in[20];
    const float* bb1  = (const float*)d_in[21];
    const float* Wb2  = (const float*)d_in[22];
    const float* bb2  = (const float*)d_in[23];
    float* out = (float*)d_out;

    float *pX, *pH, *pQKV, *pATT, *pFF, *pT1, *pT2;
    cudaGetSymbolAddress((void**)&pX,   g_X);
    cudaGetSymbolAddress((void**)&pH,   g_Hn);
    cudaGetSymbolAddress((void**)&pQKV, g_QKV);
    cudaGetSymbolAddress((void**)&pATT, g_ATT);
    cudaGetSymbolAddress((void**)&pFF,  g_FF);
    cudaGetSymbolAddress((void**)&pT1,  g_T1);
    cudaGetSymbolAddress((void**)&pT2,  g_T2);

    dim3 tb(16, 16);

    embed_kernel<<<N_TOK, HDIM>>>(x_raw, Win, b_in);
    build_nbr_kernel<<<N_TOK / 8, 256>>>();

    for (int l = 0; l < NLAYER; l++) {
        const float* Wqkv_l = Wqkv + (size_t)l * 3 * HDIM * HDIM;
        const float* bqkv_l = bqkv + (size_t)l * 3 * HDIM;
        const float* Wo_l   = Wo   + (size_t)l * HDIM * HDIM;
        const float* bo_l   = bo   + (size_t)l * HDIM;
        const float* W1_l   = W1   + (size_t)l * FFDIM * HDIM;
        const float* b1_l   = b1   + (size_t)l * FFDIM;
        const float* W2_l   = W2   + (size_t)l * HDIM * FFDIM;
        const float* b2_l   = b2   + (size_t)l * HDIM;

        ln_kernel<<<N_TOK, HDIM>>>(pX, g1 + l * HDIM, be1 + l * HDIM, pH);
        tgemm_kernel<false, false><<<dim3(768 / 64, N_TOK / 64), 128>>>(
            pH, Wqkv_l, bqkv_l, nullptr, pQKV, N_TOK, 768, HDIM);
        attn_kernel<<<(N_TOK * NHEAD * 32) / 256, 256>>>();
        tgemm_kernel<false, true><<<dim3(HDIM / 64, N_TOK / 64), 128>>>(
            pATT, Wo_l, bo_l, pX, pX, N_TOK, HDIM, HDIM);
        ln_kernel<<<N_TOK, HDIM>>>(pX, g2 + l * HDIM, be2 + l * HDIM, pH);
        tgemm_kernel<true, false><<<dim3(FFDIM / 64, N_TOK / 64), 128>>>(
            pH, W1_l, b1_l, nullptr, pFF, N_TOK, FFDIM, HDIM);
        tgemm_kernel<false, true><<<dim3(HDIM / 64, N_TOK / 64), 128>>>(
            pFF, W2_l, b2_l, pX, pX, N_TOK, HDIM, FFDIM);
    }

    // coords head: out[2048 .. 2048+49152) as [N, 24] row-major
    tgemm_kernel<true, false><<<dim3(HDIM / 64, N_TOK / 64), 128>>>(
        pX, Wl1, bl1, nullptr, pT1, N_TOK, HDIM, HDIM);
    gemm_kernel<false, false><<<dim3(1, N_TOK / 64), tb>>>(
        pT1, Wl2, bl2, nullptr, out + N_TOK, N_TOK, 24, HDIM);

    // beta head: out[0 .. 2048)
    tgemm_kernel<true, false><<<dim3(128 / 64, N_TOK / 64), 128>>>(
        pX, Wb1, bb1, nullptr, pT2, N_TOK, 128, HDIM);
    beta_kernel<<<(N_TOK * 32) / 256, 256>>>(Wb2, bb2, out);
}

// round 9
// speedup vs baseline: 1.2360x; 1.2360x over previous
#include <cuda_runtime.h>
#include <cuda_bf16.h>
#include <stdint.h>
#include <math.h>

#define N_TOK 2048
#define HDIM  256
#define NHEAD 8
#define DHEAD 32
#define FFDIM 512
#define NLAYER 6
#define CAP   96

// ---------------- device scratch ----------------
__device__ float g_X  [N_TOK * HDIM];
__device__ float g_QKV[N_TOK * 3 * HDIM];
__device__ float g_T1 [N_TOK * HDIM];
__device__ float g_T2 [N_TOK * (HDIM/2)];
__device__ float g_eta[N_TOK];
__device__ float g_phi[N_TOK];
__device__ int   g_nbr[N_TOK * CAP];
__device__ int   g_cnt[N_TOK];

// expanded bf16 operands (K' = 3K planes). A-side: [hi | lo | hi]. B-side: [hi | hi | lo].
__device__ __nv_bfloat16 g_Hexp [N_TOK * 768];    // LN output, K=256 -> K'=768
__device__ __nv_bfloat16 g_Attex[N_TOK * 768];    // attention output
__device__ __nv_bfloat16 g_Fexp [N_TOK * 1536];   // FF1 output, K=512 -> K'=1536
__device__ __nv_bfloat16 g_Xexp [N_TOK * 768];    // final X (heads)

__device__ __nv_bfloat16 g_WBqkv[NLAYER * 768 * 768];
__device__ __nv_bfloat16 g_WBo  [NLAYER * 256 * 768];
__device__ __nv_bfloat16 g_WB1  [NLAYER * 512 * 768];
__device__ __nv_bfloat16 g_WB2  [NLAYER * 256 * 1536];
__device__ __nv_bfloat16 g_WBl1 [256 * 768];
__device__ __nv_bfloat16 g_WBb1 [128 * 768];

// ---------------- helpers ----------------
__device__ __forceinline__ unsigned su32(const void* p) {
    return (unsigned)__cvta_generic_to_shared(p);
}
__device__ __forceinline__ void bf16_split(float x, __nv_bfloat16& hi, __nv_bfloat16& lo) {
    hi = __float2bfloat16(x);
    lo = __float2bfloat16(x - __bfloat162float(hi));
}
__device__ __forceinline__ void mma_bf16(float c[4],
                                         unsigned a0, unsigned a1, unsigned a2, unsigned a3,
                                         unsigned b0, unsigned b1) {
    asm volatile(
        "mma.sync.aligned.m16n8k16.row.col.f32.bf16.bf16.f32 "
        "{%0,%1,%2,%3}, {%4,%5,%6,%7}, {%8,%9}, {%0,%1,%2,%3};\n"
        : "+f"(c[0]), "+f"(c[1]), "+f"(c[2]), "+f"(c[3])
        : "r"(a0), "r"(a1), "r"(a2), "r"(a3), "r"(b0), "r"(b1));
}
__device__ __forceinline__ void ldsm_x4(unsigned r[4], unsigned addr) {
    asm volatile("ldmatrix.sync.aligned.m8n8.x4.shared.b16 {%0,%1,%2,%3}, [%4];"
                 : "=r"(r[0]), "=r"(r[1]), "=r"(r[2]), "=r"(r[3]) : "r"(addr));
}

// ---------------- weight expansion: W[l][rows][K] fp32 -> WB[l][rows][3K] bf16 ----------------
__global__ void convw_kernel(const float* __restrict__ src, __nv_bfloat16* __restrict__ dst,
                             int rows, int K, int layers) {
    long total = (long)layers * rows * K;
    for (long idx = (long)blockIdx.x * blockDim.x + threadIdx.x; idx < total;
         idx += (long)gridDim.x * blockDim.x) {
        int k = (int)(idx % K);
        long t = idx / K;
        float x = src[idx];
        __nv_bfloat16 hi, lo;
        bf16_split(x, hi, lo);
        long base = t * (3L * K);
        dst[base + k]        = hi;     // plane 0: hi
        dst[base + K + k]    = hi;     // plane 1: hi (pairs with A lo)
        dst[base + 2L*K + k] = lo;     // plane 2: lo (pairs with A hi)
    }
}

// ---------------- embed ----------------
__global__ void embed_kernel(const float* __restrict__ xr,
                             const float* __restrict__ Win,
                             const float* __restrict__ b_in) {
    int n = blockIdx.x;
    int h = threadIdx.x;               // 256
    __shared__ float r[8];
    if (h < 8) r[h] = xr[n * 8 + h];
    __syncthreads();
    float acc = b_in[h];
#pragma unroll
    for (int k = 0; k < 8; k++) acc += r[k] * Win[h * 8 + k];
    g_X[n * HDIM + h] = acc;
    if (h == 0) {
        g_eta[n] = r[1] * 5.24f   - 2.62f;
        g_phi[n] = r[2] * 6.2832f - 3.1416f;
    }
}

// ---------------- neighbor list ----------------
__global__ void build_nbr_kernel() {
    int warp = (blockIdx.x * blockDim.x + threadIdx.x) >> 5;
    int lane = threadIdx.x & 31;
    if (warp >= N_TOK) return;
    int i = warp;
    float ei = g_eta[i], pi = g_phi[i];
    int c = 0;
    for (int j0 = 0; j0 < N_TOK; j0 += 32) {
        int j = j0 + lane;
        float de = ei - g_eta[j];
        float dp = pi - g_phi[j];
        dp = dp - 6.283185307179586f * rintf(dp * 0.15915494309189535f);
        float dr2 = de * de + dp * dp;
        bool keep = (dr2 <= 0.04f);
        unsigned m = __ballot_sync(0xffffffffu, keep);
        if (keep) {
            int pos = c + __popc(m & ((1u << lane) - 1u));
            if (pos < CAP) g_nbr[i * CAP + pos] = j;
        }
        c += __popc(m);
    }
    if (lane == 0) g_cnt[i] = (c < CAP) ? c : CAP;
}

// ---------------- LayerNorm -> expanded bf16 planes ----------------
__global__ void ln_kernel(const float* __restrict__ x,
                          const float* __restrict__ g,
                          const float* __restrict__ b,
                          __nv_bfloat16* __restrict__ out) {
    int n = blockIdx.x;
    int t = threadIdx.x;               // 256
    __shared__ float r1[8], r2[8];
    float v = x[n * HDIM + t];
    float s = v;
#pragma unroll
    for (int off = 16; off; off >>= 1) s += __shfl_xor_sync(0xffffffffu, s, off);
    if ((t & 31) == 0) r1[t >> 5] = s;
    __syncthreads();
    float tot = 0.f;
#pragma unroll
    for (int w = 0; w < 8; w++) tot += r1[w];
    float mean = tot * (1.f / 256.f);
    float d = v - mean;
    float s2 = d * d;
#pragma unroll
    for (int off = 16; off; off >>= 1) s2 += __shfl_xor_sync(0xffffffffu, s2, off);
    if ((t & 31) == 0) r2[t >> 5] = s2;
    __syncthreads();
    float vtot = 0.f;
#pragma unroll
    for (int w = 0; w < 8; w++) vtot += r2[w];
    float var = vtot * (1.f / 256.f);
    float y = d * rsqrtf(var + 1e-5f) * g[t] + b[t];
    __nv_bfloat16 hi, lo;
    bf16_split(y, hi, lo);
    out[n * 768 + t]       = hi;
    out[n * 768 + 256 + t] = lo;
    out[n * 768 + 512 + t] = hi;
}

// ---------------- expand X -> Xexp (for heads) ----------------
__global__ void expand_kernel(const float* __restrict__ src, __nv_bfloat16* __restrict__ dst) {
    int n = blockIdx.x;
    int t = threadIdx.x;               // 256
    float y = src[n * 256 + t];
    __nv_bfloat16 hi, lo;
    bf16_split(y, hi, lo);
    dst[n * 768 + t]       = hi;
    dst[n * 768 + 256 + t] = lo;
    dst[n * 768 + 512 + t] = hi;
}

// ---------------- bf16 HMMA GEMM over expanded K ----------------
// D[M=2048, Ncols] = Aexp[M, Kp] @ Bexp[Ncols, Kp]^T + bias (+relu)(+resid)(+expand)
// Kp multiple of 64. Tile 64x64, BK=64, 128 threads, warps 2x2 (warp tile 32x32).
template<int RELU, int RES, int EXPAND>
__global__ void __launch_bounds__(128)
hgemm(const __nv_bfloat16* __restrict__ Aexp, const __nv_bfloat16* __restrict__ Bexp,
      const float* __restrict__ bias, const float* __restrict__ Rsrc,
      float* __restrict__ Cf, __nv_bfloat16* __restrict__ Cexp,
      int Ncols, int Kp) {
    __shared__ __align__(16) __nv_bfloat16 sA[64][72];   // pad 8 -> ldmatrix conflict-free
    __shared__ __align__(16) __nv_bfloat16 sB[64][72];

    int tid  = threadIdx.x;
    int lane = tid & 31;
    int warp = tid >> 5;
    int wm = (warp >> 1) * 32;
    int wn = (warp & 1)  * 32;
    int gq = lane >> 2;                // 0..7
    int tq = lane & 3;                 // 0..3

    int m0 = blockIdx.y * 64;
    int n0 = blockIdx.x * 64;

    float acc[2][4][4];
#pragma unroll
    for (int mt = 0; mt < 2; mt++)
#pragma unroll
        for (int nt = 0; nt < 4; nt++)
#pragma unroll
            for (int r = 0; r < 4; r++) acc[mt][nt][r] = 0.f;

    int rstride = Kp >> 3;             // row stride in uint4 (8 bf16)
    const uint4* Agl = (const uint4*)(Aexp + (size_t)m0 * Kp);
    const uint4* Bgl = (const uint4*)(Bexp + (size_t)n0 * Kp);

    // ldmatrix lane addressing (precompute row/col selectors)
    int lr8  = lane & 7;               // matrix row
    int sel  = lane >> 3;              // which 8x8 matrix
    int aRow = (sel & 1) * 8 + lr8;    // +0/+8 rows
    int aCol = (sel >> 1) * 8;         // +0/+8 k

    int nchunks = Kp >> 6;             // BK=64
    for (int ic = 0; ic < nchunks; ic++) {
        int kof = ic * 8;              // uint4 offset along K
        // load A,B chunk: 64 rows x 8 uint4 each; 4 per thread per matrix
#pragma unroll
        for (int v = 0; v < 4; v++) {
            int e = v * 128 + tid;
            int row = e >> 3, c8 = e & 7;
            *(uint4*)&sA[row][c8 * 8] = Agl[(size_t)row * rstride + kof + c8];
            *(uint4*)&sB[row][c8 * 8] = Bgl[(size_t)row * rstride + kof + c8];
        }
        __syncthreads();

#pragma unroll
        for (int kk = 0; kk < 4; kk++) {
            int kb = kk * 16;
            unsigned a[2][4], b0[4], b1[4];
#pragma unroll
            for (int mt = 0; mt < 2; mt++)
                ldsm_x4(a[mt], su32(&sA[wm + mt * 16 + aRow][kb + aCol]));
            ldsm_x4(b0, su32(&sB[wn + lane][kb]));
            ldsm_x4(b1, su32(&sB[wn + lane][kb + 8]));
#pragma unroll
            for (int mt = 0; mt < 2; mt++)
#pragma unroll
                for (int nt = 0; nt < 4; nt++)
                    mma_bf16(acc[mt][nt], a[mt][0], a[mt][1], a[mt][2], a[mt][3],
                             b0[nt], b1[nt]);
        }
        __syncthreads();
    }

    // epilogue: c0:(g,2t) c1:(g,2t+1) c2:(g+8,2t) c3:(g+8,2t+1)
#pragma unroll
    for (int mt = 0; mt < 2; mt++) {
#pragma unroll
        for (int half = 0; half < 2; half++) {
            int row = m0 + wm + mt * 16 + gq + half * 8;
#pragma unroll
            for (int nt = 0; nt < 4; nt++) {
                int col = n0 + wn + nt * 8 + 2 * tq;
                float v0 = acc[mt][nt][half * 2 + 0] + bias[col];
                float v1 = acc[mt][nt][half * 2 + 1] + bias[col + 1];
                if (RELU) { v0 = fmaxf(v0, 0.f); v1 = fmaxf(v1, 0.f); }
                if (RES) {
                    v0 += Rsrc[(size_t)row * Ncols + col];
                    v1 += Rsrc[(size_t)row * Ncols + col + 1];
                }
                if (EXPAND) {
                    __nv_bfloat16 h0, l0, h1, l1;
                    bf16_split(v0, h0, l0);
                    bf16_split(v1, h1, l1);
                    size_t b = (size_t)row * 3 * Ncols;
                    Cexp[b + col]             = h0; Cexp[b + col + 1]             = h1;
                    Cexp[b + Ncols + col]     = l0; Cexp[b + Ncols + col + 1]     = l1;
                    Cexp[b + 2 * Ncols + col] = h0; Cexp[b + 2 * Ncols + col + 1] = h1;
                } else {
                    *(float2*)&Cf[(size_t)row * Ncols + col] = make_float2(v0, v1);
                }
            }
        }
    }
}

// ---------------- sparse attention: one warp per (query, head); writes expanded ----------------
__global__ void attn_kernel() {
    int warp = (blockIdx.x * blockDim.x + threadIdx.x) >> 5;
    int lane = threadIdx.x & 31;
    int n = warp >> 3;
    int h = warp & 7;
    if (n >= N_TOK) return;
    const float scale = 0.17677669529663687f;   // 1/sqrt(32)
    float q = g_QKV[n * 768 + h * 32 + lane];
    int c = g_cnt[n];
    float m = -1e30f, s = 0.f, o = 0.f;
    for (int t = 0; t < c; t++) {
        int j = g_nbr[n * CAP + t];
        float kv = g_QKV[j * 768 + 256 + h * 32 + lane];
        float prod = q * kv;
#pragma unroll
        for (int off = 16; off; off >>= 1) prod += __shfl_xor_sync(0xffffffffu, prod, off);
        float sc = prod * scale;
        float mn = fmaxf(m, sc);
        float corr = __expf(m - mn);
        float p = __expf(sc - mn);
        s = s * corr + p;
        float v = g_QKV[j * 768 + 512 + h * 32 + lane];
        o = o * corr + p * v;
        m = mn;
    }
    float y = o / s;
    __nv_bfloat16 hi, lo;
    bf16_split(y, hi, lo);
    int col = h * 32 + lane;
    g_Attex[n * 768 + col]       = hi;
    g_Attex[n * 768 + 256 + col] = lo;
    g_Attex[n * 768 + 512 + col] = hi;
}

// ---------------- scalar tiled SGEMM (small-N coords final) ----------------
template<bool RELU, bool RES>
__global__ void gemm_kernel(const float* __restrict__ A, const float* __restrict__ B,
                            const float* __restrict__ bias, const float* __restrict__ R,
                            float* __restrict__ C, int M, int Ncols, int K) {
    __shared__ __align__(16) float As[16][68];
    __shared__ __align__(16) float Bs[16][68];
    int tx = threadIdx.x, ty = threadIdx.y;            // 16 x 16
    int tid = ty * 16 + tx;
    int m0 = blockIdx.y * 64, n0 = blockIdx.x * 64;
    int lr = tid >> 2;
    int lc = (tid & 3) * 4;

    float acc[4][4];
#pragma unroll
    for (int i = 0; i < 4; i++)
#pragma unroll
        for (int j = 0; j < 4; j++) acc[i][j] = 0.f;

    const float* Ag = A + (size_t)(m0 + lr) * K + lc;
    bool bvalid = (n0 + lr) < Ncols;
    const float* Bg = B + (size_t)(n0 + lr) * K + lc;

    for (int k0 = 0; k0 < K; k0 += 16) {
        float4 av = *(const float4*)(Ag + k0);
        float4 bv = bvalid ? *(const float4*)(Bg + k0) : make_float4(0.f, 0.f, 0.f, 0.f);
        As[lc + 0][lr] = av.x; As[lc + 1][lr] = av.y;
        As[lc + 2][lr] = av.z; As[lc + 3][lr] = av.w;
        Bs[lc + 0][lr] = bv.x; Bs[lc + 1][lr] = bv.y;
        Bs[lc + 2][lr] = bv.z; Bs[lc + 3][lr] = bv.w;
        __syncthreads();
#pragma unroll
        for (int kk = 0; kk < 16; kk++) {
            float4 a = *(const float4*)&As[kk][ty * 4];
            float4 b = *(const float4*)&Bs[kk][tx * 4];
            acc[0][0] += a.x * b.x; acc[0][1] += a.x * b.y; acc[0][2] += a.x * b.z; acc[0][3] += a.x * b.w;
            acc[1][0] += a.y * b.x; acc[1][1] += a.y * b.y; acc[1][2] += a.y * b.z; acc[1][3] += a.y * b.w;
            acc[2][0] += a.z * b.x; acc[2][1] += a.z * b.y; acc[2][2] += a.z * b.z; acc[2][3] += a.z * b.w;
            acc[3][0] += a.w * b.x; acc[3][1] += a.w * b.y; acc[3][2] += a.w * b.z; acc[3][3] += a.w * b.w;
        }
        __syncthreads();
    }

#pragma unroll
    for (int i = 0; i < 4; i++) {
        int row = m0 + ty * 4 + i;
#pragma unroll
        for (int j = 0; j < 4; j++) {
            int col = n0 + tx * 4 + j;
            if (col < Ncols) {
                float v = acc[i][j] + bias[col];
                if (RELU) v = fmaxf(v, 0.f);
                if (RES)  v += R[(size_t)row * Ncols + col];
                C[(size_t)row * Ncols + col] = v;
            }
        }
    }
}

// ---------------- beta head ----------------
__global__ void beta_kernel(const float* __restrict__ Wb2,
                            const float* __restrict__ bb2,
                            float* __restrict__ out) {
    int warp = (blockIdx.x * blockDim.x + threadIdx.x) >> 5;
    int lane = threadIdx.x & 31;
    if (warp >= N_TOK) return;
    float s = 0.f;
#pragma unroll
    for (int k = lane; k < 128; k += 32) s += g_T2[warp * 128 + k] * Wb2[k];
#pragma unroll
    for (int off = 16; off; off >>= 1) s += __shfl_xor_sync(0xffffffffu, s, off);
    if (lane == 0) {
        float z = s + bb2[0];
        float b = 1.f / (1.f + expf(-z));
        b = fminf(fmaxf(b, 1e-6f), 1.f - 1e-6f);
        out[warp] = b;
    }
}

extern "C" void kernel_launch(void* const* d_in, const int* in_sizes, int n_in,
                              void* d_out, int out_size) {
    const float* x_raw = (const float*)d_in[0];
    const float* Win  = (const float*)d_in[2];
    const float* b_in = (const float*)d_in[3];
    const float* Wqkv = (const float*)d_in[4];
    const float* bqkv = (const float*)d_in[5];
    const float* Wo   = (const float*)d_in[6];
    const float* bo   = (const float*)d_in[7];
    const float* W1   = (const float*)d_in[8];
    const float* b1   = (const float*)d_in[9];
    const float* W2   = (const float*)d_in[10];
    const float* b2   = (const float*)d_in[11];
    const float* g1   = (const float*)d_in[12];
    const float* be1  = (const float*)d_in[13];
    const float* g2   = (const float*)d_in[14];
    const float* be2  = (const float*)d_in[15];
    const float* Wl1  = (const float*)d_in[16];
    const float* bl1  = (const float*)d_in[17];
    const float* Wl2  = (const float*)d_in[18];
    const float* bl2  = (const float*)d_in[19];
    const float* Wb1  = (const float*)d_in[20];
    const float* bb1  = (const float*)d_in[21];
    const float* Wb2  = (const float*)d_in[22];
    const float* bb2  = (const float*)d_in[23];
    float* out = (float*)d_out;

    float *pX, *pQKV, *pT1, *pT2;
    cudaGetSymbolAddress((void**)&pX,   g_X);
    cudaGetSymbolAddress((void**)&pQKV, g_QKV);
    cudaGetSymbolAddress((void**)&pT1,  g_T1);
    cudaGetSymbolAddress((void**)&pT2,  g_T2);
    __nv_bfloat16 *pH, *pAtt, *pF, *pXe, *pWBqkv, *pWBo, *pWB1, *pWB2, *pWBl1, *pWBb1;
    cudaGetSymbolAddress((void**)&pH,     g_Hexp);
    cudaGetSymbolAddress((void**)&pAtt,   g_Attex);
    cudaGetSymbolAddress((void**)&pF,     g_Fexp);
    cudaGetSymbolAddress((void**)&pXe,    g_Xexp);
    cudaGetSymbolAddress((void**)&pWBqkv, g_WBqkv);
    cudaGetSymbolAddress((void**)&pWBo,   g_WBo);
    cudaGetSymbolAddress((void**)&pWB1,   g_WB1);
    cudaGetSymbolAddress((void**)&pWB2,   g_WB2);
    cudaGetSymbolAddress((void**)&pWBl1,  g_WBl1);
    cudaGetSymbolAddress((void**)&pWBb1,  g_WBb1);

    dim3 tb(16, 16);

    // weight expansion (deterministic each replay)
    convw_kernel<<<2048, 256>>>(Wqkv, pWBqkv, 768, 256, NLAYER);
    convw_kernel<<<1024, 256>>>(Wo,   pWBo,   256, 256, NLAYER);
    convw_kernel<<<2048, 256>>>(W1,   pWB1,   512, 256, NLAYER);
    convw_kernel<<<2048, 256>>>(W2,   pWB2,   256, 512, NLAYER);
    convw_kernel<<<256,  256>>>(Wl1,  pWBl1,  256, 256, 1);
    convw_kernel<<<128,  256>>>(Wb1,  pWBb1,  128, 256, 1);

    embed_kernel<<<N_TOK, HDIM>>>(x_raw, Win, b_in);
    build_nbr_kernel<<<N_TOK / 8, 256>>>();

    for (int l = 0; l < NLAYER; l++) {
        const __nv_bfloat16* WBqkv_l = pWBqkv + (size_t)l * 768 * 768;
        const __nv_bfloat16* WBo_l   = pWBo   + (size_t)l * 256 * 768;
        const __nv_bfloat16* WB1_l   = pWB1   + (size_t)l * 512 * 768;
        const __nv_bfloat16* WB2_l   = pWB2   + (size_t)l * 256 * 1536;
        const float* bqkv_l = bqkv + (size_t)l * 768;
        const float* bo_l   = bo   + (size_t)l * 256;
        const float* b1_l   = b1   + (size_t)l * 512;
        const float* b2_l   = b2   + (size_t)l * 256;

        ln_kernel<<<N_TOK, HDIM>>>(pX, g1 + l * HDIM, be1 + l * HDIM, pH);
        hgemm<0, 0, 0><<<dim3(12, 32), 128>>>(
            pH, WBqkv_l, bqkv_l, nullptr, pQKV, nullptr, 768, 768);
        attn_kernel<<<(N_TOK * NHEAD * 32) / 256, 256>>>();
        hgemm<0, 1, 0><<<dim3(4, 32), 128>>>(
            pAtt, WBo_l, bo_l, pX, pX, nullptr, 256, 768);
        ln_kernel<<<N_TOK, HDIM>>>(pX, g2 + l * HDIM, be2 + l * HDIM, pH);
        hgemm<1, 0, 1><<<dim3(8, 32), 128>>>(
            pH, WB1_l, b1_l, nullptr, nullptr, pF, 512, 768);
        hgemm<0, 1, 0><<<dim3(4, 32), 128>>>(
            pF, WB2_l, b2_l, pX, pX, nullptr, 256, 1536);
    }

    expand_kernel<<<N_TOK, HDIM>>>(pX, pXe);

    // coords head
    hgemm<1, 0, 0><<<dim3(4, 32), 128>>>(
        pXe, pWBl1, bl1, nullptr, pT1, nullptr, 256, 768);
    gemm_kernel<false, false><<<dim3(1, N_TOK / 64), tb>>>(
        pT1, Wl2, bl2, nullptr, out + N_TOK, N_TOK, 24, HDIM);

    // beta head
    hgemm<1, 0, 0><<<dim3(2, 32), 128>>>(
        pXe, pWBb1, bb1, nullptr, pT2, nullptr, 128, 768);
    beta_kernel<<<(N_TOK * 32) / 256, 256>>>(Wb2, bb2, out);
}

// round 10
// speedup vs baseline: 1.4734x; 1.1920x over previous
#include <cuda_runtime.h>
#include <cuda_bf16.h>
#include <stdint.h>
#include <math.h>

#define N_TOK 2048
#define HDIM  256
#define FFDIM 512
#define NLAYER 6
#define CAP   96

// ---------------- device scratch ----------------
__device__ float g_X  [N_TOK * HDIM];
__device__ float g_QKV[N_TOK * 3 * HDIM];
__device__ float g_ATT[N_TOK * HDIM];
__device__ float g_FF [N_TOK * FFDIM];
__device__ float g_T1 [N_TOK * HDIM];
__device__ float g_T2 [N_TOK * (HDIM/2)];
__device__ float g_eta[N_TOK];
__device__ float g_phi[N_TOK];
__device__ int   g_nbr[N_TOK * CAP];
__device__ int   g_cnt[N_TOK];

// expanded bf16 weights (K' = 3K): planes [hi | hi | lo] along K'
__device__ __nv_bfloat16 g_WBqkv[NLAYER * 768 * 768];
__device__ __nv_bfloat16 g_WBo  [NLAYER * 256 * 768];
__device__ __nv_bfloat16 g_WB1  [NLAYER * 512 * 768];
__device__ __nv_bfloat16 g_WB2  [NLAYER * 256 * 1536];
__device__ __nv_bfloat16 g_WBhd [384 * 768];          // Wl1 (256 rows) ++ Wb1 (128 rows)
__device__ float         g_bhd  [384];                // bl1 ++ bb1

// ---------------- helpers ----------------
__device__ __forceinline__ unsigned su32(const void* p) {
    return (unsigned)__cvta_generic_to_shared(p);
}
__device__ __forceinline__ void bf16_split(float x, __nv_bfloat16& hi, __nv_bfloat16& lo) {
    hi = __float2bfloat16(x);
    lo = __float2bfloat16(x - __bfloat162float(hi));
}
__device__ __forceinline__ void mma_bf16(float c[4],
                                         unsigned a0, unsigned a1, unsigned a2, unsigned a3,
                                         unsigned b0, unsigned b1) {
    asm volatile(
        "mma.sync.aligned.m16n8k16.row.col.f32.bf16.bf16.f32 "
        "{%0,%1,%2,%3}, {%4,%5,%6,%7}, {%8,%9}, {%0,%1,%2,%3};\n"
        : "+f"(c[0]), "+f"(c[1]), "+f"(c[2]), "+f"(c[3])
        : "r"(a0), "r"(a1), "r"(a2), "r"(a3), "r"(b0), "r"(b1));
}
__device__ __forceinline__ void ldsm_x4(unsigned r[4], unsigned addr) {
    asm volatile("ldmatrix.sync.aligned.m8n8.x4.shared.b16 {%0,%1,%2,%3}, [%4];"
                 : "=r"(r[0]), "=r"(r[1]), "=r"(r[2]), "=r"(r[3]) : "r"(addr));
}
__device__ __forceinline__ void cpa16(unsigned saddr, const void* g) {
    asm volatile("cp.async.ca.shared.global [%0], [%1], 16;" :: "r"(saddr), "l"(g));
}
__device__ __forceinline__ void cpa_commit() {
    asm volatile("cp.async.commit_group;" ::: "memory");
}
template<int N> __device__ __forceinline__ void cpa_wait() {
    asm volatile("cp.async.wait_group %0;" :: "n"(N) : "memory");
}

// ---------------- merged weight expansion (single launch) ----------------
__global__ void convw_all(const float* __restrict__ Wqkv, const float* __restrict__ Wo,
                          const float* __restrict__ W1,   const float* __restrict__ W2,
                          const float* __restrict__ Wl1,  const float* __restrict__ Wb1,
                          const float* __restrict__ bl1,  const float* __restrict__ bb1) {
    const long n0 = 6L * 768 * 256;          // qkv
    const long n1 = n0 + 6L * 256 * 256;     // wo
    const long n2 = n1 + 6L * 512 * 256;     // w1
    const long n3 = n2 + 6L * 256 * 512;     // w2
    const long n4 = n3 + 256L * 256;         // wl1
    const long n5 = n4 + 128L * 256;         // wb1
    const long n6 = n5 + 384;                // head bias
    for (long idx = (long)blockIdx.x * blockDim.x + threadIdx.x; idx < n6;
         idx += (long)gridDim.x * blockDim.x) {
        if (idx >= n5) {                     // bias copy
            int i = (int)(idx - n5);
            g_bhd[i] = (i < 256) ? bl1[i] : bb1[i - 256];
            continue;
        }
        const float* src; __nv_bfloat16* dst; long loc; int K;
        if (idx < n0)      { src = Wqkv; dst = g_WBqkv; loc = idx;      K = 256; }
        else if (idx < n1) { src = Wo;   dst = g_WBo;   loc = idx - n0; K = 256; }
        else if (idx < n2) { src = W1;   dst = g_WB1;   loc = idx - n1; K = 256; }
        else if (idx < n3) { src = W2;   dst = g_WB2;   loc = idx - n2; K = 512; }
        else if (idx < n4) { src = Wl1;  dst = g_WBhd;  loc = idx - n3; K = 256; }
        else               { src = Wb1;  dst = g_WBhd + 256L * 768; loc = idx - n4; K = 256; }
        int k = (int)(loc % K);
        long t = loc / K;
        float x = src[loc];
        __nv_bfloat16 hi, lo;
        bf16_split(x, hi, lo);
        long base = t * (3L * K);
        dst[base + k]        = hi;           // plane 0: hi
        dst[base + K + k]    = hi;           // plane 1: hi (pairs with A lo)
        dst[base + 2L*K + k] = lo;           // plane 2: lo (pairs with A hi)
    }
}

// ---------------- embed ----------------
__global__ void embed_kernel(const float* __restrict__ xr,
                             const float* __restrict__ Win,
                             const float* __restrict__ b_in) {
    int n = blockIdx.x;
    int h = threadIdx.x;               // 256
    __shared__ float r[8];
    if (h < 8) r[h] = xr[n * 8 + h];
    __syncthreads();
    float acc = b_in[h];
#pragma unroll
    for (int k = 0; k < 8; k++) acc += r[k] * Win[h * 8 + k];
    g_X[n * HDIM + h] = acc;
    if (h == 0) {
        g_eta[n] = r[1] * 5.24f   - 2.62f;
        g_phi[n] = r[2] * 6.2832f - 3.1416f;
    }
}

// ---------------- neighbor list ----------------
__global__ void build_nbr_kernel() {
    int warp = (blockIdx.x * blockDim.x + threadIdx.x) >> 5;
    int lane = threadIdx.x & 31;
    if (warp >= N_TOK) return;
    int i = warp;
    float ei = g_eta[i], pi = g_phi[i];
    int c = 0;
    for (int j0 = 0; j0 < N_TOK; j0 += 32) {
        int j = j0 + lane;
        float de = ei - g_eta[j];
        float dp = pi - g_phi[j];
        dp = dp - 6.283185307179586f * rintf(dp * 0.15915494309189535f);
        float dr2 = de * de + dp * dp;
        bool keep = (dr2 <= 0.04f);
        unsigned m = __ballot_sync(0xffffffffu, keep);
        if (keep) {
            int pos = c + __popc(m & ((1u << lane) - 1u));
            if (pos < CAP) g_nbr[i * CAP + pos] = j;
        }
        c += __popc(m);
    }
    if (lane == 0) g_cnt[i] = (c < CAP) ? c : CAP;
}

// ---------------- fused GEMM ----------------
// C[2048, Ncols] = op(A)[2048, K] @ WBexp[Ncols, 3K]^T + bias, where
// op(A) = LayerNorm(A) if DO_LN else A, expanded to bf16 hi/lo planes in smem.
// Tile 64x64, BK=64, 128 threads (4 warps 2x2, warp tile 32x32), cp.async 2-stage B.
// RES: C += X in-place (out0 = X). SPLIT: cols [0,256)->out0 (stride 256), [256,384)->out1 (stride 128).
template<int KDIM, int DO_LN, int RELU, int RES, int SPLIT>
__global__ void __launch_bounds__(128)
fgemm(const float* __restrict__ Asrc, const __nv_bfloat16* __restrict__ WB,
      const float* __restrict__ bias,
      const float* __restrict__ gam, const float* __restrict__ bet,
      float* __restrict__ out0, float* __restrict__ out1, int Ncols) {
    constexpr int PADK  = KDIM + 8;
    constexpr int KP    = 3 * KDIM;
    constexpr int NCH   = KP / 64;
    constexpr int SZX   = 64 * PADK * 2;        // bytes per plane buffer
    constexpr int BBUF  = 64 * 144;             // bytes per B stage (64 rows x 72 bf16)

    extern __shared__ char smem[];
    __nv_bfloat16* sXhi = (__nv_bfloat16*)smem;
    __nv_bfloat16* sXlo = (__nv_bfloat16*)(smem + SZX);
    char* sB = smem + 2 * SZX;

    int tid  = threadIdx.x;
    int lane = tid & 31;
    int warp = tid >> 5;
    int wm = (warp >> 1) * 32;
    int wn = (warp & 1)  * 32;
    int gq = lane >> 2;
    int tq = lane & 3;

    int m0 = blockIdx.y * 64;
    int n0 = blockIdx.x * 64;

    unsigned sbu = su32(sB);

    const __nv_bfloat16* Bg = WB + (size_t)n0 * KP;

    // kick B chunk 0 while we build A planes
    {
#pragma unroll
        for (int v = 0; v < 4; v++) {
            int e = v * 128 + tid;
            int row = e >> 3, c8 = e & 7;
            cpa16(sbu + row * 144 + c8 * 16, Bg + (size_t)row * KP + c8 * 8);
        }
        cpa_commit();
    }

    // ---- prologue: build hi/lo planes of op(A) in smem ----
    if (DO_LN) {
        // warp-per-row, 4 warps stride over 64 rows; KDIM == 256 here
        float gv[8], bv[8];
        *(float4*)&gv[0] = *(const float4*)&gam[lane * 8];
        *(float4*)&gv[4] = *(const float4*)&gam[lane * 8 + 4];
        *(float4*)&bv[0] = *(const float4*)&bet[lane * 8];
        *(float4*)&bv[4] = *(const float4*)&bet[lane * 8 + 4];
        for (int r = warp; r < 64; r += 4) {
            const float* row = Asrc + (size_t)(m0 + r) * 256 + lane * 8;
            float x[8];
            *(float4*)&x[0] = *(const float4*)&row[0];
            *(float4*)&x[4] = *(const float4*)&row[4];
            float s = 0.f, sq = 0.f;
#pragma unroll
            for (int j = 0; j < 8; j++) { s += x[j]; sq += x[j] * x[j]; }
#pragma unroll
            for (int off = 16; off; off >>= 1) {
                s  += __shfl_xor_sync(0xffffffffu, s,  off);
                sq += __shfl_xor_sync(0xffffffffu, sq, off);
            }
            float mean = s * (1.f / 256.f);
            float var  = sq * (1.f / 256.f) - mean * mean;
            float inv  = rsqrtf(var + 1e-5f);
            __nv_bfloat16* ph = sXhi + r * PADK + lane * 8;
            __nv_bfloat16* pl = sXlo + r * PADK + lane * 8;
#pragma unroll
            for (int j = 0; j < 8; j++) {
                float y = (x[j] - mean) * inv * gv[j] + bv[j];
                __nv_bfloat16 hi, lo;
                bf16_split(y, hi, lo);
                ph[j] = hi; pl[j] = lo;
            }
        }
    } else {
        // plain expand
        constexpr int NV = 64 * KDIM / 4;      // float4 count
        for (int e = tid; e < NV; e += 128) {
            int row = e / (KDIM / 4);
            int c4  = e % (KDIM / 4);
            float4 x = *(const float4*)(Asrc + (size_t)(m0 + row) * KDIM + c4 * 4);
            __nv_bfloat16* ph = sXhi + row * PADK + c4 * 4;
            __nv_bfloat16* pl = sXlo + row * PADK + c4 * 4;
            __nv_bfloat16 h, l;
            bf16_split(x.x, h, l); ph[0] = h; pl[0] = l;
            bf16_split(x.y, h, l); ph[1] = h; pl[1] = l;
            bf16_split(x.z, h, l); ph[2] = h; pl[2] = l;
            bf16_split(x.w, h, l); ph[3] = h; pl[3] = l;
        }
    }

    float acc[2][4][4];
#pragma unroll
    for (int mt = 0; mt < 2; mt++)
#pragma unroll
        for (int nt = 0; nt < 4; nt++)
#pragma unroll
            for (int r = 0; r < 4; r++) acc[mt][nt][r] = 0.f;

    // ldmatrix lane addressing
    int lr8 = lane & 7;
    int sel = lane >> 3;
    int aRow = (sel & 1) * 8 + lr8;
    int aCol = (sel >> 1) * 8;

    for (int ic = 0; ic < NCH; ic++) {
        if (ic + 1 < NCH) {
            int buf = (ic + 1) & 1;
#pragma unroll
            for (int v = 0; v < 4; v++) {
                int e = v * 128 + tid;
                int row = e >> 3, c8 = e & 7;
                cpa16(sbu + buf * BBUF + row * 144 + c8 * 16,
                      Bg + (size_t)row * KP + (ic + 1) * 64 + c8 * 8);
            }
            cpa_commit();
            cpa_wait<1>();
        } else {
            cpa_wait<0>();
        }
        __syncthreads();

        int kglob = ic * 64;
        int plane = kglob / KDIM;
        int k0    = kglob % KDIM;
        const __nv_bfloat16* aPl = (plane == 1) ? sXlo : sXhi;
        char* bBuf = sB + (ic & 1) * BBUF;

#pragma unroll
        for (int kk = 0; kk < 4; kk++) {
            int kb = kk * 16;
            unsigned a[2][4], b0[4], b1[4];
#pragma unroll
            for (int mt = 0; mt < 2; mt++)
                ldsm_x4(a[mt], su32(aPl + (wm + mt * 16 + aRow) * PADK + k0 + kb + aCol));
            ldsm_x4(b0, su32(bBuf + (wn + lane) * 144 + kb * 2));
            ldsm_x4(b1, su32(bBuf + (wn + lane) * 144 + kb * 2 + 16));
#pragma unroll
            for (int mt = 0; mt < 2; mt++)
#pragma unroll
                for (int nt = 0; nt < 4; nt++)
                    mma_bf16(acc[mt][nt], a[mt][0], a[mt][1], a[mt][2], a[mt][3],
                             b0[nt], b1[nt]);
        }
        __syncthreads();
    }

    // ---- epilogue ----
#pragma unroll
    for (int mt = 0; mt < 2; mt++) {
#pragma unroll
        for (int half = 0; half < 2; half++) {
            int row = m0 + wm + mt * 16 + gq + half * 8;
#pragma unroll
            for (int nt = 0; nt < 4; nt++) {
                int col = n0 + wn + nt * 8 + 2 * tq;
                float v0 = acc[mt][nt][half * 2 + 0] + bias[col];
                float v1 = acc[mt][nt][half * 2 + 1] + bias[col + 1];
                if (RELU) { v0 = fmaxf(v0, 0.f); v1 = fmaxf(v1, 0.f); }
                if (RES) {
                    float2 old = *(float2*)&out0[(size_t)row * Ncols + col];
                    v0 += old.x; v1 += old.y;
                }
                if (SPLIT) {
                    if (col < 256) {
                        *(float2*)&out0[(size_t)row * 256 + col] = make_float2(v0, v1);
                    } else {
                        *(float2*)&out1[(size_t)row * 128 + (col - 256)] = make_float2(v0, v1);
                    }
                } else {
                    *(float2*)&out0[(size_t)row * Ncols + col] = make_float2(v0, v1);
                }
            }
        }
    }
}

// ---------------- sparse attention: one warp per (query, head) ----------------
__global__ void attn_kernel() {
    int warp = (blockIdx.x * blockDim.x + threadIdx.x) >> 5;
    int lane = threadIdx.x & 31;
    int n = warp >> 3;
    int h = warp & 7;
    if (n >= N_TOK) return;
    const float scale = 0.17677669529663687f;   // 1/sqrt(32)
    float q = g_QKV[n * 768 + h * 32 + lane];
    int c = g_cnt[n];
    float m = -1e30f, s = 0.f, o = 0.f;
    for (int t = 0; t < c; t++) {
        int j = g_nbr[n * CAP + t];
        float kv = g_QKV[j * 768 + 256 + h * 32 + lane];
        float prod = q * kv;
#pragma unroll
        for (int off = 16; off; off >>= 1) prod += __shfl_xor_sync(0xffffffffu, prod, off);
        float sc = prod * scale;
        float mn = fmaxf(m, sc);
        float corr = __expf(m - mn);
        float p = __expf(sc - mn);
        s = s * corr + p;
        float v = g_QKV[j * 768 + 512 + h * 32 + lane];
        o = o * corr + p * v;
        m = mn;
    }
    g_ATT[n * 256 + h * 32 + lane] = o / s;
}

// ---------------- finals: coords (24-col gemm) + beta head, one launch ----------------
__global__ void finals_kernel(const float* __restrict__ Wl2, const float* __restrict__ bl2,
                              const float* __restrict__ Wb2, const float* __restrict__ bb2,
                              float* __restrict__ out) {
    if (blockIdx.x < 192) {
        // coords: 2048 x 24, each thread one (row, o) dot over 256
        int idx = blockIdx.x * 256 + threadIdx.x;      // < 49152
        int row = idx / 24;
        int o   = idx % 24;
        const float* a = g_T1 + (size_t)row * 256;
        const float* w = Wl2 + (size_t)o * 256;
        float s = 0.f;
#pragma unroll 8
        for (int k = 0; k < 256; k++) s += a[k] * w[k];
        out[N_TOK + (size_t)row * 24 + o] = s + bl2[o];
    } else {
        // beta: warp per row
        int b2 = blockIdx.x - 192;
        int warp = b2 * 8 + (threadIdx.x >> 5);
        int lane = threadIdx.x & 31;
        if (warp >= N_TOK) return;
        float s = 0.f;
#pragma unroll
        for (int k = lane; k < 128; k += 32) s += g_T2[warp * 128 + k] * Wb2[k];
#pragma unroll
        for (int off = 16; off; off >>= 1) s += __shfl_xor_sync(0xffffffffu, s, off);
        if (lane == 0) {
            float z = s + bb2[0];
            float b = 1.f / (1.f + expf(-z));
            b = fminf(fmaxf(b, 1e-6f), 1.f - 1e-6f);
            out[warp] = b;
        }
    }
}

extern "C" void kernel_launch(void* const* d_in, const int* in_sizes, int n_in,
                              void* d_out, int out_size) {
    const float* x_raw = (const float*)d_in[0];
    const float* Win  = (const float*)d_in[2];
    const float* b_in = (const float*)d_in[3];
    const float* Wqkv = (const float*)d_in[4];
    const float* bqkv = (const float*)d_in[5];
    const float* Wo   = (const float*)d_in[6];
    const float* bo   = (const float*)d_in[7];
    const float* W1   = (const float*)d_in[8];
    const float* b1   = (const float*)d_in[9];
    const float* W2   = (const float*)d_in[10];
    const float* b2   = (const float*)d_in[11];
    const float* g1   = (const float*)d_in[12];
    const float* be1  = (const float*)d_in[13];
    const float* g2   = (const float*)d_in[14];
    const float* be2  = (const float*)d_in[15];
    const float* Wl1  = (const float*)d_in[16];
    const float* bl1  = (const float*)d_in[17];
    const float* Wl2  = (const float*)d_in[18];
    const float* bl2  = (const float*)d_in[19];
    const float* Wb1  = (const float*)d_in[20];
    const float* bb1  = (const float*)d_in[21];
    const float* Wb2  = (const float*)d_in[22];
    const float* bb2  = (const float*)d_in[23];
    float* out = (float*)d_out;

    float *pX, *pQKV, *pATT, *pFF, *pT1, *pT2, *pbhd;
    cudaGetSymbolAddress((void**)&pX,   g_X);
    cudaGetSymbolAddress((void**)&pQKV, g_QKV);
    cudaGetSymbolAddress((void**)&pATT, g_ATT);
    cudaGetSymbolAddress((void**)&pFF,  g_FF);
    cudaGetSymbolAddress((void**)&pT1,  g_T1);
    cudaGetSymbolAddress((void**)&pT2,  g_T2);
    cudaGetSymbolAddress((void**)&pbhd, g_bhd);
    __nv_bfloat16 *pWBqkv, *pWBo, *pWB1, *pWB2, *pWBhd;
    cudaGetSymbolAddress((void**)&pWBqkv, g_WBqkv);
    cudaGetSymbolAddress((void**)&pWBo,   g_WBo);
    cudaGetSymbolAddress((void**)&pWB1,   g_WB1);
    cudaGetSymbolAddress((void**)&pWB2,   g_WB2);
    cudaGetSymbolAddress((void**)&pWBhd,  g_WBhd);

    const int SM256 = 2 * (64 * (256 + 8) * 2) + 2 * 64 * 144;   // 86016
    const int SM512 = 2 * (64 * (512 + 8) * 2) + 2 * 64 * 144;   // 151552
    cudaFuncSetAttribute(fgemm<256,1,0,0,0>, cudaFuncAttributeMaxDynamicSharedMemorySize, SM256);
    cudaFuncSetAttribute(fgemm<256,0,0,1,0>, cudaFuncAttributeMaxDynamicSharedMemorySize, SM256);
    cudaFuncSetAttribute(fgemm<256,1,1,0,0>, cudaFuncAttributeMaxDynamicSharedMemorySize, SM256);
    cudaFuncSetAttribute(fgemm<512,0,0,1,0>, cudaFuncAttributeMaxDynamicSharedMemorySize, SM512);
    cudaFuncSetAttribute(fgemm<256,0,1,0,1>, cudaFuncAttributeMaxDynamicSharedMemorySize, SM256);

    convw_all<<<2048, 256>>>(Wqkv, Wo, W1, W2, Wl1, Wb1, bl1, bb1);
    embed_kernel<<<N_TOK, HDIM>>>(x_raw, Win, b_in);
    build_nbr_kernel<<<N_TOK / 8, 256>>>();

    for (int l = 0; l < NLAYER; l++) {
        const __nv_bfloat16* WBqkv_l = pWBqkv + (size_t)l * 768 * 768;
        const __nv_bfloat16* WBo_l   = pWBo   + (size_t)l * 256 * 768;
        const __nv_bfloat16* WB1_l   = pWB1   + (size_t)l * 512 * 768;
        const __nv_bfloat16* WB2_l   = pWB2   + (size_t)l * 256 * 1536;

        // QKV = LN1(X) @ Wqkv^T + bqkv
        fgemm<256,1,0,0,0><<<dim3(12, 32), 128, SM256>>>(
            pX, WBqkv_l, bqkv + l * 768, g1 + l * 256, be1 + l * 256,
            pQKV, nullptr, 768);
        attn_kernel<<<(N_TOK * 8 * 32) / 256, 256>>>();
        // X += ATT @ Wo^T + bo
        fgemm<256,0,0,1,0><<<dim3(4, 32), 128, SM256>>>(
            pATT, WBo_l, bo + l * 256, nullptr, nullptr,
            pX, nullptr, 256);
        // FF = relu(LN2(X) @ W1^T + b1)
        fgemm<256,1,1,0,0><<<dim3(8, 32), 128, SM256>>>(
            pX, WB1_l, b1 + l * 512, g2 + l * 256, be2 + l * 256,
            pFF, nullptr, 512);
        // X += FF @ W2^T + b2
        fgemm<512,0,0,1,0><<<dim3(4, 32), 128, SM512>>>(
            pFF, WB2_l, b2 + l * 256, nullptr, nullptr,
            pX, nullptr, 256);
    }

    // heads: [T1 | T2] = relu(X @ [Wl1;Wb1]^T + [bl1;bb1])
    fgemm<256,0,1,0,1><<<dim3(6, 32), 128, SM256>>>(
        pX, pWBhd, pbhd, nullptr, nullptr,
        pT1, pT2, 384);
    finals_kernel<<<448, 256>>>(Wl2, bl2, Wb2, bb2, out);
}

// round 11
// speedup vs baseline: 1.8183x; 1.2341x over previous
#include <cuda_runtime.h>
#include <cuda_bf16.h>
#include <stdint.h>
#include <math.h>

#define N_TOK 2048
#define HDIM  256
#define FFDIM 512
#define NLAYER 6
#define CAP   96

// ---------------- device scratch ----------------
__device__ float g_X  [N_TOK * HDIM];
__device__ float g_QKV[N_TOK * 3 * HDIM];
__device__ float g_T1 [N_TOK * HDIM];
__device__ float g_T2 [N_TOK * (HDIM/2)];
__device__ float g_eta[N_TOK];
__device__ float g_phi[N_TOK];
__device__ int   g_nbr[N_TOK * CAP];
__device__ int   g_cnt[N_TOK];

// packed bf16 activation planes: row = [hi(0..K-1) | lo(0..K-1)]
__device__ __nv_bfloat16 g_Aex [N_TOK * 512];    // K=256 sources (LN out / attn out / X)
__device__ __nv_bfloat16 g_FFex[N_TOK * 1024];   // K=512 (FF1 out)

// expanded bf16 weights (K' = 3K): planes [hi | hi | lo] along K'
__device__ __nv_bfloat16 g_WBqkv[NLAYER * 768 * 768];
__device__ __nv_bfloat16 g_WBo  [NLAYER * 256 * 768];
__device__ __nv_bfloat16 g_WB1  [NLAYER * 512 * 768];
__device__ __nv_bfloat16 g_WB2  [NLAYER * 256 * 1536];
__device__ __nv_bfloat16 g_WBhd [384 * 768];     // Wl1 (256 rows) ++ Wb1 (128 rows)
__device__ float         g_bhd  [384];           // bl1 ++ bb1

// ---------------- helpers ----------------
__device__ __forceinline__ unsigned su32(const void* p) {
    return (unsigned)__cvta_generic_to_shared(p);
}
__device__ __forceinline__ void bf16_split(float x, __nv_bfloat16& hi, __nv_bfloat16& lo) {
    hi = __float2bfloat16(x);
    lo = __float2bfloat16(x - __bfloat162float(hi));
}
__device__ __forceinline__ void mma_bf16(float c[4],
                                         unsigned a0, unsigned a1, unsigned a2, unsigned a3,
                                         unsigned b0, unsigned b1) {
    asm volatile(
        "mma.sync.aligned.m16n8k16.row.col.f32.bf16.bf16.f32 "
        "{%0,%1,%2,%3}, {%4,%5,%6,%7}, {%8,%9}, {%0,%1,%2,%3};\n"
        : "+f"(c[0]), "+f"(c[1]), "+f"(c[2]), "+f"(c[3])
        : "r"(a0), "r"(a1), "r"(a2), "r"(a3), "r"(b0), "r"(b1));
}
__device__ __forceinline__ void ldsm_x4(unsigned r[4], unsigned addr) {
    asm volatile("ldmatrix.sync.aligned.m8n8.x4.shared.b16 {%0,%1,%2,%3}, [%4];"
                 : "=r"(r[0]), "=r"(r[1]), "=r"(r[2]), "=r"(r[3]) : "r"(addr));
}
__device__ __forceinline__ void cpa16(unsigned saddr, const void* g) {
    asm volatile("cp.async.ca.shared.global [%0], [%1], 16;" :: "r"(saddr), "l"(g));
}
__device__ __forceinline__ void cpa_commit() {
    asm volatile("cp.async.commit_group;" ::: "memory");
}
template<int N> __device__ __forceinline__ void cpa_wait() {
    asm volatile("cp.async.wait_group %0;" :: "n"(N) : "memory");
}

// ---------------- merged weight expansion ----------------
__global__ void convw_all(const float* __restrict__ Wqkv, const float* __restrict__ Wo,
                          const float* __restrict__ W1,   const float* __restrict__ W2,
                          const float* __restrict__ Wl1,  const float* __restrict__ Wb1,
                          const float* __restrict__ bl1,  const float* __restrict__ bb1) {
    const long n0 = 6L * 768 * 256;
    const long n1 = n0 + 6L * 256 * 256;
    const long n2 = n1 + 6L * 512 * 256;
    const long n3 = n2 + 6L * 256 * 512;
    const long n4 = n3 + 256L * 256;
    const long n5 = n4 + 128L * 256;
    const long n6 = n5 + 384;
    for (long idx = (long)blockIdx.x * blockDim.x + threadIdx.x; idx < n6;
         idx += (long)gridDim.x * blockDim.x) {
        if (idx >= n5) {
            int i = (int)(idx - n5);
            g_bhd[i] = (i < 256) ? bl1[i] : bb1[i - 256];
            continue;
        }
        const float* src; __nv_bfloat16* dst; long loc; int K;
        if (idx < n0)      { src = Wqkv; dst = g_WBqkv; loc = idx;      K = 256; }
        else if (idx < n1) { src = Wo;   dst = g_WBo;   loc = idx - n0; K = 256; }
        else if (idx < n2) { src = W1;   dst = g_WB1;   loc = idx - n1; K = 256; }
        else if (idx < n3) { src = W2;   dst = g_WB2;   loc = idx - n2; K = 512; }
        else if (idx < n4) { src = Wl1;  dst = g_WBhd;  loc = idx - n3; K = 256; }
        else               { src = Wb1;  dst = g_WBhd + 256L * 768; loc = idx - n4; K = 256; }
        int k = (int)(loc % K);
        long t = loc / K;
        float x = src[loc];
        __nv_bfloat16 hi, lo;
        bf16_split(x, hi, lo);
        long base = t * (3L * K);
        dst[base + k]        = hi;     // plane 0: hi   (pairs A-hi)
        dst[base + K + k]    = hi;     // plane 1: hi   (pairs A-lo)
        dst[base + 2L*K + k] = lo;     // plane 2: lo   (pairs A-hi)
    }
}

// ---------------- embed ----------------
__global__ void embed_kernel(const float* __restrict__ xr,
                             const float* __restrict__ Win,
                             const float* __restrict__ b_in) {
    int n = blockIdx.x;
    int h = threadIdx.x;
    __shared__ float r[8];
    if (h < 8) r[h] = xr[n * 8 + h];
    __syncthreads();
    float acc = b_in[h];
#pragma unroll
    for (int k = 0; k < 8; k++) acc += r[k] * Win[h * 8 + k];
    g_X[n * HDIM + h] = acc;
    if (h == 0) {
        g_eta[n] = r[1] * 5.24f   - 2.62f;
        g_phi[n] = r[2] * 6.2832f - 3.1416f;
    }
}

// ---------------- neighbor list ----------------
__global__ void build_nbr_kernel() {
    int warp = (blockIdx.x * blockDim.x + threadIdx.x) >> 5;
    int lane = threadIdx.x & 31;
    if (warp >= N_TOK) return;
    int i = warp;
    float ei = g_eta[i], pi = g_phi[i];
    int c = 0;
    for (int j0 = 0; j0 < N_TOK; j0 += 32) {
        int j = j0 + lane;
        float de = ei - g_eta[j];
        float dp = pi - g_phi[j];
        dp = dp - 6.283185307179586f * rintf(dp * 0.15915494309189535f);
        float dr2 = de * de + dp * dp;
        bool keep = (dr2 <= 0.04f);
        unsigned m = __ballot_sync(0xffffffffu, keep);
        if (keep) {
            int pos = c + __popc(m & ((1u << lane) - 1u));
            if (pos < CAP) g_nbr[i * CAP + pos] = j;
        }
        c += __popc(m);
    }
    if (lane == 0) g_cnt[i] = (c < CAP) ? c : CAP;
}

// ---------------- LN -> packed planes (warp per row) ----------------
__global__ void ln_expand(const float* __restrict__ x,
                          const float* __restrict__ g,
                          const float* __restrict__ b) {
    int warp = (blockIdx.x * blockDim.x + threadIdx.x) >> 5;   // row
    int lane = threadIdx.x & 31;
    if (warp >= N_TOK) return;
    const float* row = x + (size_t)warp * 256 + lane * 8;
    float v[8];
    *(float4*)&v[0] = *(const float4*)&row[0];
    *(float4*)&v[4] = *(const float4*)&row[4];
    float s = 0.f, sq = 0.f;
#pragma unroll
    for (int j = 0; j < 8; j++) { s += v[j]; sq += v[j] * v[j]; }
#pragma unroll
    for (int off = 16; off; off >>= 1) {
        s  += __shfl_xor_sync(0xffffffffu, s,  off);
        sq += __shfl_xor_sync(0xffffffffu, sq, off);
    }
    float mean = s * (1.f / 256.f);
    float var  = sq * (1.f / 256.f) - mean * mean;
    float inv  = rsqrtf(var + 1e-5f);
    __nv_bfloat16 hi[8], lo[8];
#pragma unroll
    for (int j = 0; j < 8; j++) {
        float y = (v[j] - mean) * inv * g[lane * 8 + j] + b[lane * 8 + j];
        bf16_split(y, hi[j], lo[j]);
    }
    *(uint4*)&g_Aex[(size_t)warp * 512 + lane * 8]       = *(uint4*)hi;
    *(uint4*)&g_Aex[(size_t)warp * 512 + 256 + lane * 8] = *(uint4*)lo;
}

// ---------------- plain expand X -> planes ----------------
__global__ void expand_kernel(const float* __restrict__ src) {
    int n = blockIdx.x;
    int t = threadIdx.x;
    float y = src[n * 256 + t];
    __nv_bfloat16 hi, lo;
    bf16_split(y, hi, lo);
    g_Aex[(size_t)n * 512 + t]       = hi;
    g_Aex[(size_t)n * 512 + 256 + t] = lo;
}

// ---------------- streamed dual-buffer bf16 GEMM ----------------
// C[2048, Ncols] = Aplanes[2048, K] @ WBexp[Ncols, 3K]^T + bias
// A: packed plane rows [hi(K)|lo(K)] bf16, stride 2K. B: expanded, stride 3K.
// Tile 64x64, BK=64, 256 threads (8 warps 2x4; warp tile 32x16).
template<int KDIM, int RELU, int RES, int SPLIT, int EXPAND>
__global__ void __launch_bounds__(256)
fgemm(const __nv_bfloat16* __restrict__ Aex, const __nv_bfloat16* __restrict__ WB,
      const float* __restrict__ bias,
      float* __restrict__ out0, float* __restrict__ out1,
      __nv_bfloat16* __restrict__ Cexp, int Ncols) {
    constexpr int KP   = 3 * KDIM;
    constexpr int NCH  = KP / 64;
    constexpr int ASTR = 2 * KDIM;              // bf16 stride of A plane rows

    __shared__ __nv_bfloat16 sA[2][64][72];
    __shared__ __nv_bfloat16 sB[2][64][72];

    int tid  = threadIdx.x;
    int lane = tid & 31;
    int warp = tid >> 5;
    int wm = (warp & 1) * 32;
    int wn = (warp >> 1) * 16;
    int gq = lane >> 2;
    int tq = lane & 3;

    int m0 = blockIdx.y * 64;
    int n0 = blockIdx.x * 64;

    const uint4* Ag = (const uint4*)(Aex + (size_t)m0 * ASTR);
    const uint4* Bg = (const uint4*)(WB  + (size_t)n0 * KP);

    // issue chunk ic into stage st
    auto issue = [&](int ic, int st) {
        int kglob = ic * 64;
        int plane = kglob / KDIM;
        int k0    = kglob % KDIM;
        int acol8 = ((plane == 1) ? KDIM + k0 : k0) >> 3;
        int bcol8 = kglob >> 3;
#pragma unroll
        for (int v = 0; v < 2; v++) {
            int e = v * 256 + tid;
            int row = e >> 3, c8 = e & 7;
            cpa16(su32(&sA[st][row][c8 * 8]), Ag + (size_t)row * (ASTR >> 3) + acol8 + c8);
            cpa16(su32(&sB[st][row][c8 * 8]), Bg + (size_t)row * (KP >> 3)   + bcol8 + c8);
        }
        cpa_commit();
    };
    issue(0, 0);

    float acc[2][2][4];
#pragma unroll
    for (int mt = 0; mt < 2; mt++)
#pragma unroll
        for (int nt = 0; nt < 2; nt++)
#pragma unroll
            for (int r = 0; r < 4; r++) acc[mt][nt][r] = 0.f;

    int lr8 = lane & 7;
    int sel = lane >> 3;
    int aRow = (sel & 1) * 8 + lr8;
    int aCol = (sel >> 1) * 8;
    int bRow = lane & 15;
    int bCol = (lane >> 4) * 8;

    for (int ic = 0; ic < NCH; ic++) {
        if (ic + 1 < NCH) { issue(ic + 1, (ic + 1) & 1); cpa_wait<1>(); }
        else              { cpa_wait<0>(); }
        __syncthreads();
        int st = ic & 1;
#pragma unroll
        for (int kk = 0; kk < 4; kk++) {
            int kb = kk * 16;
            unsigned a[2][4], b[4];
            ldsm_x4(a[0], su32(&sA[st][wm + aRow][kb + aCol]));
            ldsm_x4(a[1], su32(&sA[st][wm + 16 + aRow][kb + aCol]));
            ldsm_x4(b,    su32(&sB[st][wn + bRow][kb + bCol]));
#pragma unroll
            for (int mt = 0; mt < 2; mt++) {
                mma_bf16(acc[mt][0], a[mt][0], a[mt][1], a[mt][2], a[mt][3], b[0], b[2]);
                mma_bf16(acc[mt][1], a[mt][0], a[mt][1], a[mt][2], a[mt][3], b[1], b[3]);
            }
        }
        __syncthreads();
    }

    // epilogue
#pragma unroll
    for (int mt = 0; mt < 2; mt++) {
#pragma unroll
        for (int half = 0; half < 2; half++) {
            int row = m0 + wm + mt * 16 + gq + half * 8;
#pragma unroll
            for (int nt = 0; nt < 2; nt++) {
                int col = n0 + wn + nt * 8 + 2 * tq;
                float v0 = acc[mt][nt][half * 2 + 0] + bias[col];
                float v1 = acc[mt][nt][half * 2 + 1] + bias[col + 1];
                if (RELU) { v0 = fmaxf(v0, 0.f); v1 = fmaxf(v1, 0.f); }
                if (RES) {
                    float2 old = *(float2*)&out0[(size_t)row * Ncols + col];
                    v0 += old.x; v1 += old.y;
                }
                if (EXPAND) {
                    // FF1: write packed planes, stride 2*Ncols
                    __nv_bfloat16 h0, l0, h1, l1;
                    bf16_split(v0, h0, l0);
                    bf16_split(v1, h1, l1);
                    size_t base = (size_t)row * 2 * Ncols;
                    Cexp[base + col]             = h0;
                    Cexp[base + col + 1]         = h1;
                    Cexp[base + Ncols + col]     = l0;
                    Cexp[base + Ncols + col + 1] = l1;
                } else if (SPLIT) {
                    if (col < 256) *(float2*)&out0[(size_t)row * 256 + col] = make_float2(v0, v1);
                    else           *(float2*)&out1[(size_t)row * 128 + (col - 256)] = make_float2(v0, v1);
                } else {
                    *(float2*)&out0[(size_t)row * Ncols + col] = make_float2(v0, v1);
                }
            }
        }
    }
}

// ---------------- sparse attention: warp per (query, head); writes planes ----------------
__global__ void attn_kernel() {
    int warp = (blockIdx.x * blockDim.x + threadIdx.x) >> 5;
    int lane = threadIdx.x & 31;
    int n = warp >> 3;
    int h = warp & 7;
    if (n >= N_TOK) return;
    const float scale = 0.17677669529663687f;   // 1/sqrt(32)
    float q = g_QKV[n * 768 + h * 32 + lane];
    int c = g_cnt[n];
    float m = -1e30f, s = 0.f, o = 0.f;
    for (int t = 0; t < c; t++) {
        int j = g_nbr[n * CAP + t];
        float kv = g_QKV[j * 768 + 256 + h * 32 + lane];
        float prod = q * kv;
#pragma unroll
        for (int off = 16; off; off >>= 1) prod += __shfl_xor_sync(0xffffffffu, prod, off);
        float sc = prod * scale;
        float mn = fmaxf(m, sc);
        float corr = __expf(m - mn);
        float p = __expf(sc - mn);
        s = s * corr + p;
        float v = g_QKV[j * 768 + 512 + h * 32 + lane];
        o = o * corr + p * v;
        m = mn;
    }
    float y = o / s;
    __nv_bfloat16 hi, lo;
    bf16_split(y, hi, lo);
    int col = h * 32 + lane;
    g_Aex[(size_t)n * 512 + col]       = hi;
    g_Aex[(size_t)n * 512 + 256 + col] = lo;
}

// ---------------- finals: coords (24-col gemm) + beta head ----------------
__global__ void finals_kernel(const float* __restrict__ Wl2, const float* __restrict__ bl2,
                              const float* __restrict__ Wb2, const float* __restrict__ bb2,
                              float* __restrict__ out) {
    if (blockIdx.x < 192) {
        int idx = blockIdx.x * 256 + threadIdx.x;
        int row = idx / 24;
        int o   = idx % 24;
        const float* a = g_T1 + (size_t)row * 256;
        const float* w = Wl2 + (size_t)o * 256;
        float s = 0.f;
#pragma unroll 8
        for (int k = 0; k < 256; k++) s += a[k] * w[k];
        out[N_TOK + (size_t)row * 24 + o] = s + bl2[o];
    } else {
        int b2 = blockIdx.x - 192;
        int warp = b2 * 8 + (threadIdx.x >> 5);
        int lane = threadIdx.x & 31;
        if (warp >= N_TOK) return;
        float s = 0.f;
#pragma unroll
        for (int k = lane; k < 128; k += 32) s += g_T2[warp * 128 + k] * Wb2[k];
#pragma unroll
        for (int off = 16; off; off >>= 1) s += __shfl_xor_sync(0xffffffffu, s, off);
        if (lane == 0) {
            float z = s + bb2[0];
            float b = 1.f / (1.f + expf(-z));
            b = fminf(fmaxf(b, 1e-6f), 1.f - 1e-6f);
            out[warp] = b;
        }
    }
}

extern "C" void kernel_launch(void* const* d_in, const int* in_sizes, int n_in,
                              void* d_out, int out_size) {
    const float* x_raw = (const float*)d_in[0];
    const float* Win  = (const float*)d_in[2];
    const float* b_in = (const float*)d_in[3];
    const float* Wqkv = (const float*)d_in[4];
    const float* bqkv = (const float*)d_in[5];
    const float* Wo   = (const float*)d_in[6];
    const float* bo   = (const float*)d_in[7];
    const float* W1   = (const float*)d_in[8];
    const float* b1   = (const float*)d_in[9];
    const float* W2   = (const float*)d_in[10];
    const float* b2   = (const float*)d_in[11];
    const float* g1   = (const float*)d_in[12];
    const float* be1  = (const float*)d_in[13];
    const float* g2   = (const float*)d_in[14];
    const float* be2  = (const float*)d_in[15];
    const float* Wl1  = (const float*)d_in[16];
    const float* bl1  = (const float*)d_in[17];
    const float* Wl2  = (const float*)d_in[18];
    const float* bl2  = (const float*)d_in[19];
    const float* Wb1  = (const float*)d_in[20];
    const float* bb1  = (const float*)d_in[21];
    const float* Wb2  = (const float*)d_in[22];
    const float* bb2  = (const float*)d_in[23];
    float* out = (float*)d_out;

    float *pX, *pQKV, *pT1, *pT2, *pbhd;
    cudaGetSymbolAddress((void**)&pX,   g_X);
    cudaGetSymbolAddress((void**)&pQKV, g_QKV);
    cudaGetSymbolAddress((void**)&pT1,  g_T1);
    cudaGetSymbolAddress((void**)&pT2,  g_T2);
    cudaGetSymbolAddress((void**)&pbhd, g_bhd);
    __nv_bfloat16 *pAex, *pFFex, *pWBqkv, *pWBo, *pWB1, *pWB2, *pWBhd;
    cudaGetSymbolAddress((void**)&pAex,   g_Aex);
    cudaGetSymbolAddress((void**)&pFFex,  g_FFex);
    cudaGetSymbolAddress((void**)&pWBqkv, g_WBqkv);
    cudaGetSymbolAddress((void**)&pWBo,   g_WBo);
    cudaGetSymbolAddress((void**)&pWB1,   g_WB1);
    cudaGetSymbolAddress((void**)&pWB2,   g_WB2);
    cudaGetSymbolAddress((void**)&pWBhd,  g_WBhd);

    convw_all<<<2048, 256>>>(Wqkv, Wo, W1, W2, Wl1, Wb1, bl1, bb1);
    embed_kernel<<<N_TOK, HDIM>>>(x_raw, Win, b_in);
    build_nbr_kernel<<<N_TOK / 8, 256>>>();

    for (int l = 0; l < NLAYER; l++) {
        const __nv_bfloat16* WBqkv_l = pWBqkv + (size_t)l * 768 * 768;
        const __nv_bfloat16* WBo_l   = pWBo   + (size_t)l * 256 * 768;
        const __nv_bfloat16* WB1_l   = pWB1   + (size_t)l * 512 * 768;
        const __nv_bfloat16* WB2_l   = pWB2   + (size_t)l * 256 * 1536;

        ln_expand<<<N_TOK / 8, 256>>>(pX, g1 + l * 256, be1 + l * 256);
        fgemm<256,0,0,0,0><<<dim3(12, 32), 256>>>(
            pAex, WBqkv_l, bqkv + l * 768, pQKV, nullptr, nullptr, 768);
        attn_kernel<<<(N_TOK * 8 * 32) / 256, 256>>>();
        fgemm<256,0,1,0,0><<<dim3(4, 32), 256>>>(
            pAex, WBo_l, bo + l * 256, pX, nullptr, nullptr, 256);
        ln_expand<<<N_TOK / 8, 256>>>(pX, g2 + l * 256, be2 + l * 256);
        fgemm<256,1,0,0,1><<<dim3(8, 32), 256>>>(
            pAex, WB1_l, b1 + l * 512, nullptr, nullptr, pFFex, 512);
        fgemm<512,0,1,0,0><<<dim3(4, 32), 256>>>(
            pFFex, WB2_l, b2 + l * 256, pX, nullptr, nullptr, 256);
    }

    // heads
    expand_kernel<<<N_TOK, HDIM>>>(pX);
    fgemm<256,1,0,1,0><<<dim3(6, 32), 256>>>(
        pAex, pWBhd, pbhd, pT1, pT2, nullptr, 384);
    finals_kernel<<<448, 256>>>(Wl2, bl2, Wb2, bb2, out);
}